// round 15
// baseline (speedup 1.0000x reference)
#include <cuda_runtime.h>
#include <cuda_bf16.h>
#include <math.h>

#define B     32
#define HID   4096
#define NH    32
#define NKV   8
#define HS    128
#define BSZ   16
#define MAXS  2048
#define MAXB  128
#define G     4
#define QKVN  (HID + 2*NKV*HS)   /* 6144 */
#define SPLIT 8
#define CHUNK 256
#define TS    16
#define KSQ   3                   /* k-split for qkv gemm  (48*3 = 144 blocks) */
#define KSO   4                   /* k-split for out gemm  (32*4 = 128 blocks) */
#define KCHUNK_Q 1376             /* 1376,1376,1344 — all multiples of 32 */

#define SCALE 0.08838834764831845f   /* 128^-0.5 */

__device__ float g_gp[KSQ][B][QKVN];         // GEMM k-split partials (>= KSO*B*HID floats, reused by out-proj)
__device__ float g_qkv[B][QKVN];             // q | k | v (q,k roped in place by rope_kernel)
__device__ float g_attn[B][HID];             // attention output (pre O-proj)
__device__ float g_pm[B*NKV*G*SPLIT];        // split-KV partial max
__device__ float g_pl[B*NKV*G*SPLIT];        // split-KV partial sum
__device__ float g_pacc[B*NKV*G*SPLIT][HS];  // split-KV partial acc

// ---------- packed fp32x2 helpers (FFMA2: 2x fp32 MAC rate on sm_103a) ----------
__device__ __forceinline__ void ffma2(unsigned long long &acc, unsigned long long a, unsigned long long b){
    asm("fma.rn.f32x2 %0, %1, %2, %0;" : "+l"(acc) : "l"(a), "l"(b));
}
__device__ __forceinline__ unsigned long long mul2(unsigned long long a, unsigned long long b){
    unsigned long long r; asm("mul.rn.f32x2 %0, %1, %2;" : "=l"(r) : "l"(a), "l"(b)); return r;
}
__device__ __forceinline__ unsigned long long dup2(float x){
    unsigned long long r; asm("mov.b64 %0, {%1, %1};" : "=l"(r) : "f"(x)); return r;
}
__device__ __forceinline__ float2 unpk(unsigned long long v){
    float2 r; asm("mov.b64 {%0, %1}, %2;" : "=f"(r.x), "=f"(r.y) : "l"(v)); return r;
}
// ---------- cp.async helpers ----------
__device__ __forceinline__ void cpa16(void* s, const void* g){
    unsigned ss = (unsigned)__cvta_generic_to_shared(s);
    asm volatile("cp.async.cg.shared.global [%0], [%1], 16;" :: "r"(ss), "l"(g));
}
#define CPA_COMMIT() asm volatile("cp.async.commit_group;")
#define CPA_WAIT(n)  asm volatile("cp.async.wait_group %0;" :: "n"(n))

// ---------- skinny GEMM tile: Y[0:32, n0:n0+128] over K slice [k0, k0+kb) ----------
// Thread (tx=tid&31, ty=tid>>5): 4 m-rows x 4 n-cols.  Register-prefetched staging.
__device__ __forceinline__ void gemm_tile(const float* __restrict__ X, const float* __restrict__ W,
                                          float* __restrict__ Y, int K, int ldY, int n0, int wrow0,
                                          int k0, int kb)
{
    __shared__ unsigned long long xs[32][36];  // [k][m] dup-pairs {v,v}
    __shared__ float ws[32][132];              // [k][n] transposed W tile

    const int tid = threadIdx.x;
    const int tx = tid & 31;
    const int ty = tid >> 5;

    unsigned long long a00=0, a01=0, a10=0, a11=0;
    unsigned long long a20=0, a21=0, a30=0, a31=0;

    const int lm = tid >> 3, lc = tid & 7;   // X loader
    const int wn = tid >> 1, wq = tid & 1;   // W loader
    const float* Xp = X + (size_t)lm*K + k0 + 4*lc;
    const float* Wp = W + (size_t)(wrow0 + wn)*K + k0;

    float4 xv = *(const float4*)(Xp);
    float4 wv0 = *(const float4*)(Wp + 4*(wq*4+0));
    float4 wv1 = *(const float4*)(Wp + 4*(wq*4+1));
    float4 wv2 = *(const float4*)(Wp + 4*(wq*4+2));
    float4 wv3 = *(const float4*)(Wp + 4*(wq*4+3));

    for (int kt = 0; kt < kb; kt += 32) {
        xs[4*lc+0][lm] = dup2(xv.x); xs[4*lc+1][lm] = dup2(xv.y);
        xs[4*lc+2][lm] = dup2(xv.z); xs[4*lc+3][lm] = dup2(xv.w);
        {
            int c0q = wq*4;
            ws[4*c0q+0][wn]  = wv0.x; ws[4*c0q+1][wn]  = wv0.y; ws[4*c0q+2][wn]  = wv0.z; ws[4*c0q+3][wn]  = wv0.w;
            ws[4*c0q+4][wn]  = wv1.x; ws[4*c0q+5][wn]  = wv1.y; ws[4*c0q+6][wn]  = wv1.z; ws[4*c0q+7][wn]  = wv1.w;
            ws[4*c0q+8][wn]  = wv2.x; ws[4*c0q+9][wn]  = wv2.y; ws[4*c0q+10][wn] = wv2.z; ws[4*c0q+11][wn] = wv2.w;
            ws[4*c0q+12][wn] = wv3.x; ws[4*c0q+13][wn] = wv3.y; ws[4*c0q+14][wn] = wv3.z; ws[4*c0q+15][wn] = wv3.w;
        }
        __syncthreads();
        if (kt + 32 < kb) {       // prefetch next slice while computing this one
            xv  = *(const float4*)(Xp + kt + 32);
            wv0 = *(const float4*)(Wp + kt + 32 + 4*(wq*4+0));
            wv1 = *(const float4*)(Wp + kt + 32 + 4*(wq*4+1));
            wv2 = *(const float4*)(Wp + kt + 32 + 4*(wq*4+2));
            wv3 = *(const float4*)(Wp + kt + 32 + 4*(wq*4+3));
        }
        #pragma unroll
        for (int k = 0; k < 32; k++) {
            ulonglong2 wv  = *(const ulonglong2*)&ws[k][4*tx];
            ulonglong2 b01 = *(const ulonglong2*)&xs[k][4*ty];
            ulonglong2 b23 = *(const ulonglong2*)&xs[k][4*ty+2];
            ffma2(a00, wv.x, b01.x); ffma2(a01, wv.y, b01.x);
            ffma2(a10, wv.x, b01.y); ffma2(a11, wv.y, b01.y);
            ffma2(a20, wv.x, b23.x); ffma2(a21, wv.y, b23.x);
            ffma2(a30, wv.x, b23.y); ffma2(a31, wv.y, b23.y);
        }
        __syncthreads();
    }
    #pragma unroll
    for (int i = 0; i < 4; i++) {
        unsigned long long p0, p1;
        if (i == 0)      { p0 = a00; p1 = a01; }
        else if (i == 1) { p0 = a10; p1 = a11; }
        else if (i == 2) { p0 = a20; p1 = a21; }
        else             { p0 = a30; p1 = a31; }
        float2 r0 = unpk(p0), r1 = unpk(p1);
        float* yp = Y + (size_t)(4*ty + i)*ldY + n0 + 4*tx;
        *(float4*)yp = make_float4(r0.x, r0.y, r1.x, r1.y);
    }
}

__global__ void __launch_bounds__(256) qkv_gemm(const float* __restrict__ x,
                                                const float* __restrict__ wq,
                                                const float* __restrict__ wk,
                                                const float* __restrict__ wv)
{
    int n0 = blockIdx.x * 128;
    const float* W; int wr;
    if (n0 < HID)                 { W = wq; wr = n0; }
    else if (n0 < HID + NKV*HS)   { W = wk; wr = n0 - HID; }
    else                          { W = wv; wr = n0 - HID - NKV*HS; }
    int k0 = blockIdx.y * KCHUNK_Q;
    int kb = min(KCHUNK_Q, HID - k0);
    gemm_tile(x, W, &g_gp[blockIdx.y][0][0], HID, QKVN, n0, wr, k0, kb);
}

__global__ void __launch_bounds__(256) out_gemm(const float* __restrict__ wo)
{
    int n0 = blockIdx.x * 128;
    int k0 = blockIdx.y * (HID / KSO);
    gemm_tile(&g_attn[0][0], wo, &g_gp[0][0][0] + (size_t)blockIdx.y * (B*HID), HID, HID,
              n0, n0, k0, HID / KSO);
}

__global__ void __launch_bounds__(256) reduce_qkv()
{
    int i = blockIdx.x * 256 + threadIdx.x;
    if (i < B*QKVN) {
        const float* p = &g_gp[0][0][0];
        const int S = B*QKVN;
        (&g_qkv[0][0])[i] = p[i] + p[i + S] + p[i + 2*S];
    }
}

__global__ void __launch_bounds__(256) reduce_out(float* __restrict__ out)
{
    int i = blockIdx.x * 256 + threadIdx.x;
    if (i < B*HID) {
        const float* p = &g_gp[0][0][0];
        const int S = B*HID;
        out[i] = (p[i] + p[i + S]) + (p[i + 2*S] + p[i + 3*S]);
    }
}

// ---------- RoPE applied once, in place: q (scaled) and k in g_qkv ----------
__global__ void __launch_bounds__(128) rope_kernel(const int* __restrict__ lens)
{
    const int b = blockIdx.x;
    const int tid = threadIdx.x;
    __shared__ float cb[64], sb[64];
    const float pos = (float)(lens[b] - 1);
    if (tid < 64) {
        float inv = powf(10000.0f, -(float)tid * (1.0f/64.0f));
        float f = pos * inv, s, c;
        sincosf(f, &s, &c);
        cb[tid] = c; sb[tid] = s;
    }
    __syncthreads();
    // q: NH*64 rotation pairs, fold in softmax scale
    for (int idx = tid; idx < NH*64; idx += 128) {
        int h = idx >> 6, d0 = idx & 63;
        float* qp = &g_qkv[b][h*HS];
        float x1 = qp[d0], x2 = qp[d0+64];
        float c = cb[d0], s = sb[d0];
        qp[d0]    = (x1*c - x2*s) * SCALE;
        qp[d0+64] = (x2*c + x1*s) * SCALE;
    }
    // k: NKV*64 rotation pairs
    for (int idx = tid; idx < NKV*64; idx += 128) {
        int h = idx >> 6, d0 = idx & 63;
        float* kp = &g_qkv[b][HID + h*HS];
        float x1 = kp[d0], x2 = kp[d0+64];
        float c = cb[d0], s = sb[d0];
        kp[d0]    = x1*c - x2*s;
        kp[d0+64] = x2*c + x1*s;
    }
}

// pads so qkv_gemm is the ncu-captured launch (#4)
__global__ void profile_pad1() {}
__global__ void profile_pad2() {}
__global__ void profile_pad3() {}

// ---------- split-KV flash-decoding attention ----------
// grid (NKV, SPLIT, B), 128 threads; warp g handles query group g.
// TS=16 double-buffered cp.async staging; rotation-swizzled tiles.
// q/k already roped (and q scaled) by rope_kernel.
__global__ void __launch_bounds__(128) attn_kernel(const float* __restrict__ kc,
                                                   const float* __restrict__ vc,
                                                   const int* __restrict__ bt,
                                                   const int* __restrict__ lens)
{
    const int kv = blockIdx.x, chunk = blockIdx.y, b = blockIdx.z;
    const int tid = threadIdx.x;
    const int lane = tid & 31;
    const int g = tid >> 5;

    const int len  = lens[b];
    const int last = len - 1;
    const int pidx = ((b*NKV + kv)*G + g)*SPLIT + chunk;
    const int c0 = chunk * CHUNK;

    if (c0 >= len) {
        if (lane == 0) { g_pm[pidx] = -INFINITY; g_pl[pidx] = 0.f; }
        float4 z = make_float4(0.f, 0.f, 0.f, 0.f);
        *(float4*)&g_pacc[pidx][4*lane] = z;
        return;
    }

    __shared__ float qs[G][HS];
    __shared__ float knew[HS], vnew[HS];
    __shared__ float ks[2][TS][HS], vs[2][TS][HS];   // double-buffered, rotation-swizzled

    // load roped+scaled q, roped knew, raw vnew (pure float4 copies)
    {
        const float4* qp = (const float4*)&g_qkv[b][(kv*G + g)*HS];
        ((float4*)&qs[g][0])[lane] = qp[lane];
    }
    if (g == 0) {
        const float4* kp = (const float4*)&g_qkv[b][HID + kv*HS];
        ((float4*)knew)[lane] = kp[lane];
    } else if (g == 1) {
        const float4* vp = (const float4*)&g_qkv[b][HID + NKV*HS + kv*HS];
        ((float4*)vnew)[lane] = vp[lane];
    }
    __syncthreads();

    const int cend      = min(c0 + CHUNK, len);
    const int cache_end = min(cend, last);
    const int ntiles    = (cache_end > c0) ? (cache_end - c0 + TS - 1) / TS : 0;

    float m = -INFINITY, l = 0.f;
    unsigned long long a01a=0, a23a=0, a01b=0, a23b=0;   // lane owns cols 4*lane..+3
    const int* btb = bt + b*MAXB;

    const int srow = tid >> 3;          // staging: row 0..15
    const int sq0  = (tid & 7) * 4;     // 4 quads per thread per tensor

    // stage tile i into buffer i&1  (rotation swizzle: physical quad = (q + row) & 31)
    #define STAGE(i) do {                                                        \
        int t0_ = c0 + (i)*TS;                                                   \
        int nt_ = min(TS, cache_end - t0_);                                      \
        int bi_ = (i) & 1;                                                       \
        if (srow < nt_) {                                                        \
            int s_ = t0_ + srow;                                                 \
            int row_ = btb[s_ >> 4]*BSZ + (s_ & 15);                             \
            const float4* kr_ = (const float4*)(kc + ((size_t)row_*NKV + kv)*HS);\
            const float4* vr_ = (const float4*)(vc + ((size_t)row_*NKV + kv)*HS);\
            _Pragma("unroll")                                                    \
            for (int i2 = 0; i2 < 4; i2++) {                                     \
                int q_ = sq0 + i2; int pq_ = (q_ + srow) & 31;                   \
                cpa16(&ks[bi_][srow][4*pq_], kr_ + q_);                          \
                cpa16(&vs[bi_][srow][4*pq_], vr_ + q_);                          \
            }                                                                    \
        }                                                                        \
    } while (0)

    if (ntiles > 0) STAGE(0);
    CPA_COMMIT();

    const int pos  = lane & 15;
    const int half = lane >> 4;

    for (int i = 0; i < ntiles; i++) {
        if (i + 1 < ntiles) STAGE(i + 1);
        CPA_COMMIT();
        if (i + 1 < ntiles) CPA_WAIT(1); else CPA_WAIT(0);
        __syncthreads();

        const int bi = i & 1;
        const int t0 = c0 + i*TS;
        const int nt = min(TS, cache_end - t0);

        // QK: lane pair (pos, pos+16) splits the 128-dim dot (quads half*16..half*16+15)
        float sc;
        {
            const float* kr = &ks[bi][pos][0];
            const ulonglong2* qp2 = (const ulonglong2*)&qs[g][0];
            unsigned long long s0=0, s1=0, s2=0, s3=0;
            #pragma unroll
            for (int q = 0; q < 16; q += 2) {
                int q0 = half*16 + q;
                ulonglong2 kk0 = *(const ulonglong2*)(kr + 4*((q0 + pos) & 31));
                ulonglong2 qq0 = qp2[q0];
                ffma2(s0, kk0.x, qq0.x); ffma2(s1, kk0.y, qq0.y);
                ulonglong2 kk1 = *(const ulonglong2*)(kr + 4*((q0 + 1 + pos) & 31));
                ulonglong2 qq1 = qp2[q0+1];
                ffma2(s2, kk1.x, qq1.x); ffma2(s3, kk1.y, qq1.y);
            }
            float2 f0 = unpk(s0), f1 = unpk(s1), f2 = unpk(s2), f3 = unpk(s3);
            float part = ((f0.x + f0.y) + (f1.x + f1.y)) + ((f2.x + f2.y) + (f3.x + f3.y));
            sc = part + __shfl_xor_sync(0xffffffffu, part, 16);
            if (pos >= nt) sc = -INFINITY;
        }

        float tm = sc;
        #pragma unroll
        for (int o = 8; o; o >>= 1) tm = fmaxf(tm, __shfl_xor_sync(0xffffffffu, tm, o));
        float nm = fmaxf(m, tm);
        float corr = __expf(m - nm);
        float p = __expf(sc - nm);                      // 0 for masked positions
        float ps = p;
        #pragma unroll
        for (int o = 8; o; o >>= 1) ps += __shfl_xor_sync(0xffffffffu, ps, o);
        l = l*corr + ps;
        m = nm;
        {
            unsigned long long c2 = dup2(corr);
            a01a = mul2(a01a, c2); a23a = mul2(a23a, c2);
            a01b = mul2(a01b, c2); a23b = mul2(a23b, c2);
        }

        #pragma unroll 8
        for (int r = 0; r < nt; r++) {
            float pr = __shfl_sync(0xffffffffu, p, r);   // lane r holds p for position r
            unsigned long long pd = dup2(pr);
            ulonglong2 vv = *(const ulonglong2*)(&vs[bi][r][0] + 4*((lane + r) & 31));
            if (r & 1) { ffma2(a01b, vv.x, pd); ffma2(a23b, vv.y, pd); }
            else       { ffma2(a01a, vv.x, pd); ffma2(a23a, vv.y, pd); }
        }
        __syncthreads();
    }

    // append the freshly-written token if it falls in this chunk
    if (last >= c0 && last < cend) {
        const float4* kn4 = (const float4*)knew;
        const float4* qp4 = (const float4*)&qs[g][0];
        float sc = 0.f;
        #pragma unroll
        for (int i = 0; i < 32; i++) {
            float4 kk = kn4[i], qq = qp4[i];
            sc += kk.x*qq.x + kk.y*qq.y + kk.z*qq.z + kk.w*qq.w;
        }
        float nm = fmaxf(m, sc);
        float corr = __expf(m - nm);
        float p = __expf(sc - nm);
        l = l*corr + p;
        m = nm;
        unsigned long long c2 = dup2(corr), pd = dup2(p);
        a01a = mul2(a01a, c2); a23a = mul2(a23a, c2);
        a01b = mul2(a01b, c2); a23b = mul2(a23b, c2);
        ulonglong2 vv = *(const ulonglong2*)(vnew + 4*lane);
        ffma2(a01a, vv.x, pd); ffma2(a23a, vv.y, pd);
    }

    if (lane == 0) { g_pm[pidx] = m; g_pl[pidx] = l; }
    {
        float2 xa = unpk(a01a), xb = unpk(a01b), ya = unpk(a23a), yb = unpk(a23b);
        float4 outp = make_float4(xa.x + xb.x, xa.y + xb.y, ya.x + yb.x, ya.y + yb.y);
        *(float4*)&g_pacc[pidx][4*lane] = outp;
    }
    #undef STAGE
}

// ---------- combine split-KV partials ----------
__global__ void __launch_bounds__(128) combine_kernel()
{
    const int kv = blockIdx.x, b = blockIdx.y;
    const int tid = threadIdx.x, lane = tid & 31, g = tid >> 5;
    const int p0 = ((b*NKV + kv)*G + g)*SPLIT;

    float M = -INFINITY;
    #pragma unroll
    for (int c = 0; c < SPLIT; c++) M = fmaxf(M, g_pm[p0 + c]);

    float L = 0.f;
    float4 o = make_float4(0.f, 0.f, 0.f, 0.f);
    #pragma unroll
    for (int c = 0; c < SPLIT; c++) {
        float pm = g_pm[p0 + c];
        float w = (pm == -INFINITY) ? 0.f : __expf(pm - M);
        L += g_pl[p0 + c] * w;
        float4 a = *(const float4*)&g_pacc[p0 + c][4*lane];
        o.x += a.x*w; o.y += a.y*w; o.z += a.z*w; o.w += a.w*w;
    }
    float inv = 1.0f / L;
    float4 r = make_float4(o.x*inv, o.y*inv, o.z*inv, o.w*inv);
    *(float4*)&g_attn[b][(kv*G + g)*HS + 4*lane] = r;
}

extern "C" void kernel_launch(void* const* d_in, const int* in_sizes, int n_in,
                              void* d_out, int out_size)
{
    const float* hs   = (const float*)d_in[0];
    const float* wq   = (const float*)d_in[1];
    const float* wk   = (const float*)d_in[2];
    const float* wv   = (const float*)d_in[3];
    const float* wo   = (const float*)d_in[4];
    const float* kc   = (const float*)d_in[5];
    const float* vc   = (const float*)d_in[6];
    const int*   bt   = (const int*)d_in[8];
    const int*   lens = (const int*)d_in[10];
    float* out = (float*)d_out;

    profile_pad1<<<1, 32>>>();
    profile_pad2<<<1, 32>>>();
    profile_pad3<<<1, 32>>>();                      // qkv_gemm becomes launch #4 (ncu capture slot)
    qkv_gemm<<<dim3(QKVN/128, KSQ), 256>>>(hs, wq, wk, wv);
    reduce_qkv<<<(B*QKVN + 255)/256, 256>>>();
    rope_kernel<<<B, 128>>>(lens);
    attn_kernel<<<dim3(NKV, SPLIT, B), 128>>>(kc, vc, bt, lens);
    combine_kernel<<<dim3(NKV, B), 128>>>();
    out_gemm<<<dim3(HID/128, KSO), 256>>>(wo);
    reduce_out<<<(B*HID + 255)/256, 256>>>(out);
}

// round 17
// speedup vs baseline: 1.1362x; 1.1362x over previous
#include <cuda_runtime.h>
#include <cuda_bf16.h>
#include <math.h>

#define B     32
#define HID   4096
#define NH    32
#define NKV   8
#define HS    128
#define BSZ   16
#define MAXS  2048
#define MAXB  128
#define G     4
#define QKVN  (HID + 2*NKV*HS)   /* 6144 */
#define SPLIT 8
#define CHUNK 256
#define TS    16
#define KSQ   6                   /* k-split for qkv gemm  (48*6 = 288 blocks ~ 2/SM) */
#define KSO   8                   /* k-split for out gemm  (32*8 = 256 blocks) */
#define KCHUNK_Q 704              /* 704*5 + 576 = 4096; all multiples of 32 */

#define SCALE 0.08838834764831845f   /* 128^-0.5 */

__device__ float g_gp[KSQ][B][QKVN];         // GEMM k-split partials (>= KSO*B*HID floats, reused by out-proj)
__device__ float g_qkv[B][QKVN];             // q | k | v (q,k roped in place by rope_kernel)
__device__ float g_attn[B][HID];             // attention output (pre O-proj)
__device__ float g_pm[B*NKV*G*SPLIT];        // split-KV partial max
__device__ float g_pl[B*NKV*G*SPLIT];        // split-KV partial sum
__device__ float g_pacc[B*NKV*G*SPLIT][HS];  // split-KV partial acc

// ---------- packed fp32x2 helpers (FFMA2: 2x fp32 MAC rate on sm_103a) ----------
__device__ __forceinline__ void ffma2(unsigned long long &acc, unsigned long long a, unsigned long long b){
    asm("fma.rn.f32x2 %0, %1, %2, %0;" : "+l"(acc) : "l"(a), "l"(b));
}
__device__ __forceinline__ unsigned long long mul2(unsigned long long a, unsigned long long b){
    unsigned long long r; asm("mul.rn.f32x2 %0, %1, %2;" : "=l"(r) : "l"(a), "l"(b)); return r;
}
__device__ __forceinline__ unsigned long long dup2(float x){
    unsigned long long r; asm("mov.b64 %0, {%1, %1};" : "=l"(r) : "f"(x)); return r;
}
__device__ __forceinline__ float2 unpk(unsigned long long v){
    float2 r; asm("mov.b64 {%0, %1}, %2;" : "=f"(r.x), "=f"(r.y) : "l"(v)); return r;
}
// ---------- cp.async helpers ----------
__device__ __forceinline__ void cpa16(void* s, const void* g){
    unsigned ss = (unsigned)__cvta_generic_to_shared(s);
    asm volatile("cp.async.cg.shared.global [%0], [%1], 16;" :: "r"(ss), "l"(g));
}
#define CPA_COMMIT() asm volatile("cp.async.commit_group;")
#define CPA_WAIT(n)  asm volatile("cp.async.wait_group %0;" :: "n"(n))

// ---------- skinny GEMM tile: Y[0:32, n0:n0+128] over K slice [k0, k0+kb) ----------
// Thread (tx=tid&31, ty=tid>>5): 4 m-rows x 4 n-cols.  Register-prefetched staging.
__device__ __forceinline__ void gemm_tile(const float* __restrict__ X, const float* __restrict__ W,
                                          float* __restrict__ Y, int K, int ldY, int n0, int wrow0,
                                          int k0, int kb)
{
    __shared__ unsigned long long xs[32][36];  // [k][m] dup-pairs {v,v}
    __shared__ float ws[32][132];              // [k][n] transposed W tile

    const int tid = threadIdx.x;
    const int tx = tid & 31;
    const int ty = tid >> 5;

    unsigned long long a00=0, a01=0, a10=0, a11=0;
    unsigned long long a20=0, a21=0, a30=0, a31=0;

    const int lm = tid >> 3, lc = tid & 7;   // X loader
    const int wn = tid >> 1, wq = tid & 1;   // W loader
    const float* Xp = X + (size_t)lm*K + k0 + 4*lc;
    const float* Wp = W + (size_t)(wrow0 + wn)*K + k0;

    float4 xv = *(const float4*)(Xp);
    float4 wv0 = *(const float4*)(Wp + 4*(wq*4+0));
    float4 wv1 = *(const float4*)(Wp + 4*(wq*4+1));
    float4 wv2 = *(const float4*)(Wp + 4*(wq*4+2));
    float4 wv3 = *(const float4*)(Wp + 4*(wq*4+3));

    for (int kt = 0; kt < kb; kt += 32) {
        xs[4*lc+0][lm] = dup2(xv.x); xs[4*lc+1][lm] = dup2(xv.y);
        xs[4*lc+2][lm] = dup2(xv.z); xs[4*lc+3][lm] = dup2(xv.w);
        {
            int c0q = wq*4;
            ws[4*c0q+0][wn]  = wv0.x; ws[4*c0q+1][wn]  = wv0.y; ws[4*c0q+2][wn]  = wv0.z; ws[4*c0q+3][wn]  = wv0.w;
            ws[4*c0q+4][wn]  = wv1.x; ws[4*c0q+5][wn]  = wv1.y; ws[4*c0q+6][wn]  = wv1.z; ws[4*c0q+7][wn]  = wv1.w;
            ws[4*c0q+8][wn]  = wv2.x; ws[4*c0q+9][wn]  = wv2.y; ws[4*c0q+10][wn] = wv2.z; ws[4*c0q+11][wn] = wv2.w;
            ws[4*c0q+12][wn] = wv3.x; ws[4*c0q+13][wn] = wv3.y; ws[4*c0q+14][wn] = wv3.z; ws[4*c0q+15][wn] = wv3.w;
        }
        __syncthreads();
        if (kt + 32 < kb) {       // prefetch next slice while computing this one
            xv  = *(const float4*)(Xp + kt + 32);
            wv0 = *(const float4*)(Wp + kt + 32 + 4*(wq*4+0));
            wv1 = *(const float4*)(Wp + kt + 32 + 4*(wq*4+1));
            wv2 = *(const float4*)(Wp + kt + 32 + 4*(wq*4+2));
            wv3 = *(const float4*)(Wp + kt + 32 + 4*(wq*4+3));
        }
        #pragma unroll
        for (int k = 0; k < 32; k++) {
            ulonglong2 wv  = *(const ulonglong2*)&ws[k][4*tx];
            ulonglong2 b01 = *(const ulonglong2*)&xs[k][4*ty];
            ulonglong2 b23 = *(const ulonglong2*)&xs[k][4*ty+2];
            ffma2(a00, wv.x, b01.x); ffma2(a01, wv.y, b01.x);
            ffma2(a10, wv.x, b01.y); ffma2(a11, wv.y, b01.y);
            ffma2(a20, wv.x, b23.x); ffma2(a21, wv.y, b23.x);
            ffma2(a30, wv.x, b23.y); ffma2(a31, wv.y, b23.y);
        }
        __syncthreads();
    }
    #pragma unroll
    for (int i = 0; i < 4; i++) {
        unsigned long long p0, p1;
        if (i == 0)      { p0 = a00; p1 = a01; }
        else if (i == 1) { p0 = a10; p1 = a11; }
        else if (i == 2) { p0 = a20; p1 = a21; }
        else             { p0 = a30; p1 = a31; }
        float2 r0 = unpk(p0), r1 = unpk(p1);
        float* yp = Y + (size_t)(4*ty + i)*ldY + n0 + 4*tx;
        *(float4*)yp = make_float4(r0.x, r0.y, r1.x, r1.y);
    }
}

__global__ void __launch_bounds__(256) qkv_gemm(const float* __restrict__ x,
                                                const float* __restrict__ wq,
                                                const float* __restrict__ wk,
                                                const float* __restrict__ wv)
{
    int n0 = blockIdx.x * 128;
    const float* W; int wr;
    if (n0 < HID)                 { W = wq; wr = n0; }
    else if (n0 < HID + NKV*HS)   { W = wk; wr = n0 - HID; }
    else                          { W = wv; wr = n0 - HID - NKV*HS; }
    int k0 = blockIdx.y * KCHUNK_Q;
    int kb = min(KCHUNK_Q, HID - k0);          // 704..704,576
    gemm_tile(x, W, &g_gp[blockIdx.y][0][0], HID, QKVN, n0, wr, k0, kb);
}

__global__ void __launch_bounds__(256) out_gemm(const float* __restrict__ wo)
{
    int n0 = blockIdx.x * 128;
    int k0 = blockIdx.y * (HID / KSO);         // kb = 512
    gemm_tile(&g_attn[0][0], wo, &g_gp[0][0][0] + (size_t)blockIdx.y * (B*HID), HID, HID,
              n0, n0, k0, HID / KSO);
}

__global__ void __launch_bounds__(256) reduce_qkv()
{
    int i = blockIdx.x * 256 + threadIdx.x;
    if (i < B*QKVN) {
        const float* p = &g_gp[0][0][0];
        const int S = B*QKVN;
        float a = (p[i] + p[i + S]) + (p[i + 2*S] + p[i + 3*S]);
        float b2 = p[i + 4*S] + p[i + 5*S];
        (&g_qkv[0][0])[i] = a + b2;
    }
}

__global__ void __launch_bounds__(256) reduce_out(float* __restrict__ out)
{
    int i = blockIdx.x * 256 + threadIdx.x;
    if (i < B*HID) {
        const float* p = &g_gp[0][0][0];
        const int S = B*HID;
        float a = (p[i] + p[i + S]) + (p[i + 2*S] + p[i + 3*S]);
        float b2 = (p[i + 4*S] + p[i + 5*S]) + (p[i + 6*S] + p[i + 7*S]);
        out[i] = a + b2;
    }
}

// ---------- RoPE applied once, in place: q (scaled) and k in g_qkv ----------
__global__ void __launch_bounds__(128) rope_kernel(const int* __restrict__ lens)
{
    const int b = blockIdx.x;
    const int tid = threadIdx.x;
    __shared__ float cb[64], sb[64];
    const float pos = (float)(lens[b] - 1);
    if (tid < 64) {
        float inv = powf(10000.0f, -(float)tid * (1.0f/64.0f));
        float f = pos * inv, s, c;
        sincosf(f, &s, &c);
        cb[tid] = c; sb[tid] = s;
    }
    __syncthreads();
    for (int idx = tid; idx < NH*64; idx += 128) {
        int h = idx >> 6, d0 = idx & 63;
        float* qp = &g_qkv[b][h*HS];
        float x1 = qp[d0], x2 = qp[d0+64];
        float c = cb[d0], s = sb[d0];
        qp[d0]    = (x1*c - x2*s) * SCALE;
        qp[d0+64] = (x2*c + x1*s) * SCALE;
    }
    for (int idx = tid; idx < NKV*64; idx += 128) {
        int h = idx >> 6, d0 = idx & 63;
        float* kp = &g_qkv[b][HID + h*HS];
        float x1 = kp[d0], x2 = kp[d0+64];
        float c = cb[d0], s = sb[d0];
        kp[d0]    = x1*c - x2*s;
        kp[d0+64] = x2*c + x1*s;
    }
}

// pads so qkv_gemm is the ncu-captured launch (#4)
__global__ void profile_pad1() {}
__global__ void profile_pad2() {}
__global__ void profile_pad3() {}

// ---------- split-KV flash-decoding attention ----------
// grid (NKV, SPLIT, B), 128 threads; warp g handles query group g.
// TS=16 double-buffered cp.async staging; rotation-swizzled tiles.
// q/k already roped (and q scaled) by rope_kernel.
__global__ void __launch_bounds__(128) attn_kernel(const float* __restrict__ kc,
                                                   const float* __restrict__ vc,
                                                   const int* __restrict__ bt,
                                                   const int* __restrict__ lens)
{
    const int kv = blockIdx.x, chunk = blockIdx.y, b = blockIdx.z;
    const int tid = threadIdx.x;
    const int lane = tid & 31;
    const int g = tid >> 5;

    const int len  = lens[b];
    const int last = len - 1;
    const int pidx = ((b*NKV + kv)*G + g)*SPLIT + chunk;
    const int c0 = chunk * CHUNK;

    if (c0 >= len) {
        if (lane == 0) { g_pm[pidx] = -INFINITY; g_pl[pidx] = 0.f; }
        float4 z = make_float4(0.f, 0.f, 0.f, 0.f);
        *(float4*)&g_pacc[pidx][4*lane] = z;
        return;
    }

    __shared__ float qs[G][HS];
    __shared__ float knew[HS], vnew[HS];
    __shared__ float ks[2][TS][HS], vs[2][TS][HS];   // double-buffered, rotation-swizzled

    // load roped+scaled q, roped knew, raw vnew (pure float4 copies)
    {
        const float4* qp = (const float4*)&g_qkv[b][(kv*G + g)*HS];
        ((float4*)&qs[g][0])[lane] = qp[lane];
    }
    if (g == 0) {
        const float4* kp = (const float4*)&g_qkv[b][HID + kv*HS];
        ((float4*)knew)[lane] = kp[lane];
    } else if (g == 1) {
        const float4* vp = (const float4*)&g_qkv[b][HID + NKV*HS + kv*HS];
        ((float4*)vnew)[lane] = vp[lane];
    }
    __syncthreads();

    const int cend      = min(c0 + CHUNK, len);
    const int cache_end = min(cend, last);
    const int ntiles    = (cache_end > c0) ? (cache_end - c0 + TS - 1) / TS : 0;

    float m = -INFINITY, l = 0.f;
    unsigned long long a01a=0, a23a=0, a01b=0, a23b=0;   // lane owns cols 4*lane..+3
    const int* btb = bt + b*MAXB;

    const int srow = tid >> 3;          // staging: row 0..15
    const int sq0  = (tid & 7) * 4;     // 4 quads per thread per tensor

    #define STAGE(i) do {                                                        \
        int t0_ = c0 + (i)*TS;                                                   \
        int nt_ = min(TS, cache_end - t0_);                                      \
        int bi_ = (i) & 1;                                                       \
        if (srow < nt_) {                                                        \
            int s_ = t0_ + srow;                                                 \
            int row_ = btb[s_ >> 4]*BSZ + (s_ & 15);                             \
            const float4* kr_ = (const float4*)(kc + ((size_t)row_*NKV + kv)*HS);\
            const float4* vr_ = (const float4*)(vc + ((size_t)row_*NKV + kv)*HS);\
            _Pragma("unroll")                                                    \
            for (int i2 = 0; i2 < 4; i2++) {                                     \
                int q_ = sq0 + i2; int pq_ = (q_ + srow) & 31;                   \
                cpa16(&ks[bi_][srow][4*pq_], kr_ + q_);                          \
                cpa16(&vs[bi_][srow][4*pq_], vr_ + q_);                          \
            }                                                                    \
        }                                                                        \
    } while (0)

    if (ntiles > 0) STAGE(0);
    CPA_COMMIT();

    const int pos  = lane & 15;
    const int half = lane >> 4;

    for (int i = 0; i < ntiles; i++) {
        if (i + 1 < ntiles) STAGE(i + 1);
        CPA_COMMIT();
        if (i + 1 < ntiles) CPA_WAIT(1); else CPA_WAIT(0);
        __syncthreads();

        const int bi = i & 1;
        const int t0 = c0 + i*TS;
        const int nt = min(TS, cache_end - t0);

        // QK: lane pair (pos, pos+16) splits the 128-dim dot
        float sc;
        {
            const float* kr = &ks[bi][pos][0];
            const ulonglong2* qp2 = (const ulonglong2*)&qs[g][0];
            unsigned long long s0=0, s1=0, s2=0, s3=0;
            #pragma unroll
            for (int q = 0; q < 16; q += 2) {
                int q0 = half*16 + q;
                ulonglong2 kk0 = *(const ulonglong2*)(kr + 4*((q0 + pos) & 31));
                ulonglong2 qq0 = qp2[q0];
                ffma2(s0, kk0.x, qq0.x); ffma2(s1, kk0.y, qq0.y);
                ulonglong2 kk1 = *(const ulonglong2*)(kr + 4*((q0 + 1 + pos) & 31));
                ulonglong2 qq1 = qp2[q0+1];
                ffma2(s2, kk1.x, qq1.x); ffma2(s3, kk1.y, qq1.y);
            }
            float2 f0 = unpk(s0), f1 = unpk(s1), f2 = unpk(s2), f3 = unpk(s3);
            float part = ((f0.x + f0.y) + (f1.x + f1.y)) + ((f2.x + f2.y) + (f3.x + f3.y));
            sc = part + __shfl_xor_sync(0xffffffffu, part, 16);
            if (pos >= nt) sc = -INFINITY;
        }

        float tm = sc;
        #pragma unroll
        for (int o = 8; o; o >>= 1) tm = fmaxf(tm, __shfl_xor_sync(0xffffffffu, tm, o));
        float nm = fmaxf(m, tm);
        float corr = __expf(m - nm);
        float p = __expf(sc - nm);
        float ps = p;
        #pragma unroll
        for (int o = 8; o; o >>= 1) ps += __shfl_xor_sync(0xffffffffu, ps, o);
        l = l*corr + ps;
        m = nm;
        {
            unsigned long long c2 = dup2(corr);
            a01a = mul2(a01a, c2); a23a = mul2(a23a, c2);
            a01b = mul2(a01b, c2); a23b = mul2(a23b, c2);
        }

        #pragma unroll 8
        for (int r = 0; r < nt; r++) {
            float pr = __shfl_sync(0xffffffffu, p, r);
            unsigned long long pd = dup2(pr);
            ulonglong2 vv = *(const ulonglong2*)(&vs[bi][r][0] + 4*((lane + r) & 31));
            if (r & 1) { ffma2(a01b, vv.x, pd); ffma2(a23b, vv.y, pd); }
            else       { ffma2(a01a, vv.x, pd); ffma2(a23a, vv.y, pd); }
        }
        __syncthreads();
    }

    if (last >= c0 && last < cend) {
        const float4* kn4 = (const float4*)knew;
        const float4* qp4 = (const float4*)&qs[g][0];
        float sc = 0.f;
        #pragma unroll
        for (int i = 0; i < 32; i++) {
            float4 kk = kn4[i], qq = qp4[i];
            sc += kk.x*qq.x + kk.y*qq.y + kk.z*qq.z + kk.w*qq.w;
        }
        float nm = fmaxf(m, sc);
        float corr = __expf(m - nm);
        float p = __expf(sc - nm);
        l = l*corr + p;
        m = nm;
        unsigned long long c2 = dup2(corr), pd = dup2(p);
        a01a = mul2(a01a, c2); a23a = mul2(a23a, c2);
        a01b = mul2(a01b, c2); a23b = mul2(a23b, c2);
        ulonglong2 vv = *(const ulonglong2*)(vnew + 4*lane);
        ffma2(a01a, vv.x, pd); ffma2(a23a, vv.y, pd);
    }

    if (lane == 0) { g_pm[pidx] = m; g_pl[pidx] = l; }
    {
        float2 xa = unpk(a01a), xb = unpk(a01b), ya = unpk(a23a), yb = unpk(a23b);
        float4 outp = make_float4(xa.x + xb.x, xa.y + xb.y, ya.x + yb.x, ya.y + yb.y);
        *(float4*)&g_pacc[pidx][4*lane] = outp;
    }
    #undef STAGE
}

// ---------- combine split-KV partials ----------
__global__ void __launch_bounds__(128) combine_kernel()
{
    const int kv = blockIdx.x, b = blockIdx.y;
    const int tid = threadIdx.x, lane = tid & 31, g = tid >> 5;
    const int p0 = ((b*NKV + kv)*G + g)*SPLIT;

    float M = -INFINITY;
    #pragma unroll
    for (int c = 0; c < SPLIT; c++) M = fmaxf(M, g_pm[p0 + c]);

    float L = 0.f;
    float4 o = make_float4(0.f, 0.f, 0.f, 0.f);
    #pragma unroll
    for (int c = 0; c < SPLIT; c++) {
        float pm = g_pm[p0 + c];
        float w = (pm == -INFINITY) ? 0.f : __expf(pm - M);
        L += g_pl[p0 + c] * w;
        float4 a = *(const float4*)&g_pacc[p0 + c][4*lane];
        o.x += a.x*w; o.y += a.y*w; o.z += a.z*w; o.w += a.w*w;
    }
    float inv = 1.0f / L;
    float4 r = make_float4(o.x*inv, o.y*inv, o.z*inv, o.w*inv);
    *(float4*)&g_attn[b][(kv*G + g)*HS + 4*lane] = r;
}

extern "C" void kernel_launch(void* const* d_in, const int* in_sizes, int n_in,
                              void* d_out, int out_size)
{
    const float* hs   = (const float*)d_in[0];
    const float* wq   = (const float*)d_in[1];
    const float* wk   = (const float*)d_in[2];
    const float* wv   = (const float*)d_in[3];
    const float* wo   = (const float*)d_in[4];
    const float* kc   = (const float*)d_in[5];
    const float* vc   = (const float*)d_in[6];
    const int*   bt   = (const int*)d_in[8];
    const int*   lens = (const int*)d_in[10];
    float* out = (float*)d_out;

    profile_pad1<<<1, 32>>>();
    profile_pad2<<<1, 32>>>();
    profile_pad3<<<1, 32>>>();                      // qkv_gemm stays launch #4 (ncu capture slot)
    qkv_gemm<<<dim3(QKVN/128, KSQ), 256>>>(hs, wq, wk, wv);
    reduce_qkv<<<(B*QKVN + 255)/256, 256>>>();
    rope_kernel<<<B, 128>>>(lens);
    attn_kernel<<<dim3(NKV, SPLIT, B), 128>>>(kc, vc, bt, lens);
    combine_kernel<<<dim3(NKV, B), 128>>>();
    out_gemm<<<dim3(HID/128, KSO), 256>>>(wo);
    reduce_out<<<(B*HID + 255)/256, 256>>>(out);
}